// round 12
// baseline (speedup 1.0000x reference)
#include <cuda_runtime.h>
#include <cuda_fp16.h>
#include <cstdint>

#define M_TOTAL 16384
#define K_DIM   4096
#define N_DIM   4096
#define BM 128
#define BN 128
#define BK 128                               // k elements per stage (128 B of fp8)
#define STAGES 3
#define KITERS (K_DIM / BK)                  // 32
#define A_STAGE_BYTES (BM * BK)              // 16 KB
#define B_STAGE_BYTES (BN * BK)              // 16 KB
#define STAGE_BYTES (A_STAGE_BYTES + B_STAGE_BYTES)
#define SMEM_BYTES (STAGES * STAGE_BYTES)    // 96 KB

// e4m3 copies of the operands (scratch: static device arrays)
__device__ __align__(128) unsigned char g_qx[(size_t)M_TOTAL * K_DIM];  // 64 MB
__device__ __align__(128) unsigned char g_qw[(size_t)N_DIM * K_DIM];    // 16 MB

__device__ __forceinline__ uint32_t smem_u32(const void* p) {
    uint32_t a;
    asm("{ .reg .u64 t; cvta.to.shared.u64 t, %1; cvt.u32.u64 %0, t; }" : "=r"(a) : "l"(p));
    return a;
}
__device__ __forceinline__ uint32_t swz(uint32_t off) {
    return off ^ ((off >> 3) & 0x70);  // SW128 for 128-byte rows
}

#define LDMATRIX_X4(r0, r1, r2, r3, addr) \
    asm volatile("ldmatrix.sync.aligned.m8n8.x4.shared.b16 {%0,%1,%2,%3}, [%4];" \
        : "=r"(r0), "=r"(r1), "=r"(r2), "=r"(r3) : "r"(addr))
// fp8 e4m3 MMA, fp32 accumulate: D[16x8] += A[16x32] * B[32x8]
#define MMA16832(c, a, b0, b1) \
    asm volatile("mma.sync.aligned.m16n8k32.row.col.f32.e4m3.e4m3.f32 " \
        "{%0,%1,%2,%3}, {%4,%5,%6,%7}, {%8,%9}, {%0,%1,%2,%3};" \
        : "+f"((c)[0]), "+f"((c)[1]), "+f"((c)[2]), "+f"((c)[3]) \
        : "r"((a)[0]), "r"((a)[1]), "r"((a)[2]), "r"((a)[3]), "r"(b0), "r"(b1))

// ---- fused quantize: fp32 -> e4m3 (RN satfinite == clip(+-448)+RN cast) ----
#define XBLKS 2048
#define WBLKS 512
__global__ void quant_kernel(const float4* __restrict__ xsrc, const float4* __restrict__ wsrc,
                             const float* __restrict__ sp) {
    if (blockIdx.x < XBLKS) {
        float inv = 1.0f / sp[0];
        uint32_t* dst = reinterpret_cast<uint32_t*>(g_qx);
        int n4 = (M_TOTAL * K_DIM) / 4;
        int stride = XBLKS * blockDim.x;
        for (int i = blockIdx.x * blockDim.x + threadIdx.x; i < n4; i += stride) {
            float4 v = xsrc[i];
            unsigned short lo, hi;
            asm("cvt.rn.satfinite.e4m3x2.f32 %0, %1, %2;" : "=h"(lo) : "f"(v.y * inv), "f"(v.x * inv));
            asm("cvt.rn.satfinite.e4m3x2.f32 %0, %1, %2;" : "=h"(hi) : "f"(v.w * inv), "f"(v.z * inv));
            dst[i] = (uint32_t)lo | ((uint32_t)hi << 16);
        }
    } else {
        uint32_t* dst = reinterpret_cast<uint32_t*>(g_qw);
        int n4 = (N_DIM * K_DIM) / 4;
        int stride = WBLKS * blockDim.x;
        for (int i = (blockIdx.x - XBLKS) * blockDim.x + threadIdx.x; i < n4; i += stride) {
            float4 v = wsrc[i];
            unsigned short lo, hi;
            asm("cvt.rn.satfinite.e4m3x2.f32 %0, %1, %2;" : "=h"(lo) : "f"(v.y), "f"(v.x));
            asm("cvt.rn.satfinite.e4m3x2.f32 %0, %1, %2;" : "=h"(hi) : "f"(v.w), "f"(v.z));
            dst[i] = (uint32_t)lo | ((uint32_t)hi << 16);
        }
    }
}

// fill one pipeline stage: A tile [BM][BK], B tile [BN][BK], fp8, K-contig, SW128
__device__ __forceinline__ void load_stage(uint32_t sbase, int m0, int n0, int k0, int tid) {
    const char* gA = reinterpret_cast<const char*>(g_qx);
    const char* gB = reinterpret_cast<const char*>(g_qw);
#pragma unroll
    for (int j = 0; j < 4; j++) {          // A: 128 rows x 128B = 1024 x 16B chunks
        int idx = tid + j * 256;
        int row = idx >> 3, cb = (idx & 7) << 4;
        uint32_t dst = sbase + swz((uint32_t)(row * 128 + cb));
        const char* src = gA + (size_t)(m0 + row) * K_DIM + k0 + cb;
        asm volatile("cp.async.cg.shared.global [%0], [%1], 16;" :: "r"(dst), "l"(src));
    }
    uint32_t bbase = sbase + A_STAGE_BYTES;
#pragma unroll
    for (int j = 0; j < 4; j++) {          // B: 128 rows x 128B
        int idx = tid + j * 256;
        int row = idx >> 3, cb = (idx & 7) << 4;
        uint32_t dst = bbase + swz((uint32_t)(row * 128 + cb));
        const char* src = gB + (size_t)(n0 + row) * K_DIM + k0 + cb;
        asm volatile("cp.async.cg.shared.global [%0], [%1], 16;" :: "r"(dst), "l"(src));
    }
    asm volatile("cp.async.commit_group;" ::: "memory");
}

__global__ void __launch_bounds__(256, 2)
gemm_kernel(float* __restrict__ out, const float* __restrict__ bias,
            const float* __restrict__ ws_p, const float* __restrict__ is_p,
            const float* __restrict__ os_p)
{
    extern __shared__ unsigned char smem[];
    uint32_t sb = smem_u32(smem);
    int tid = threadIdx.x, lane = tid & 31, wid = tid >> 5;
    int warp_m = wid & 3, warp_n = wid >> 2;   // 4x2 warp grid, warp tile 32x64

    // supertile: groups of 8 m-tiles x 32 n-tiles keep W L2-resident
    int g = blockIdx.x >> 8, r = blockIdx.x & 255;
    int m0 = ((g << 3) + (r & 7)) * BM;
    int n0 = (r >> 3) * BN;

    load_stage(sb + 0 * STAGE_BYTES, m0, n0, 0 * BK, tid);
    load_stage(sb + 1 * STAGE_BYTES, m0, n0, 1 * BK, tid);

    float acc[2][8][4];
#pragma unroll
    for (int i = 0; i < 2; i++)
#pragma unroll
        for (int j = 0; j < 8; j++)
#pragma unroll
            for (int k = 0; k < 4; k++) acc[i][j][k] = 0.0f;

#pragma unroll 1
    for (int it = 0; it < KITERS; it++) {
        if (it < KITERS - 1) asm volatile("cp.async.wait_group 1;" ::: "memory");
        else                 asm volatile("cp.async.wait_group 0;" ::: "memory");
        __syncthreads();

        uint32_t abase = sb + (it % STAGES) * STAGE_BYTES;
        uint32_t bbase = abase + A_STAGE_BYTES;
#pragma unroll
        for (int ks = 0; ks < BK / 32; ks++) {   // 4 k-chunks of 32 e4m3
            uint32_t af[2][4], bf[4][4];
            uint32_t cb = (uint32_t)(ks * 32 + ((lane >> 4) << 4));
#pragma unroll
            for (int mt = 0; mt < 2; mt++) {
                uint32_t row = (uint32_t)(warp_m * 32 + mt * 16 + (lane & 15));
                uint32_t addr = abase + swz(row * 128 + cb);
                LDMATRIX_X4(af[mt][0], af[mt][1], af[mt][2], af[mt][3], addr);
            }
#pragma unroll
            for (int p = 0; p < 4; p++) {
                uint32_t row = (uint32_t)(warp_n * 64 + p * 16 + (lane & 15));
                uint32_t addr = bbase + swz(row * 128 + cb);
                // B stored [N][K] (K contiguous) == col-major KxN -> non-trans ldmatrix
                LDMATRIX_X4(bf[p][0], bf[p][1], bf[p][2], bf[p][3], addr);
            }
#pragma unroll
            for (int mt = 0; mt < 2; mt++)
#pragma unroll
                for (int nt = 0; nt < 8; nt++)
                    MMA16832(acc[mt][nt], af[mt], bf[nt >> 1][nt & 1], bf[nt >> 1][2 + (nt & 1)]);

            // issue next-stage cp.async AFTER the first k-slice (overlaps tensor-busy cycles)
            if (ks == 0 && it + 2 < KITERS)
                load_stage(sb + ((it + 2) % STAGES) * STAGE_BYTES, m0, n0, (it + 2) * BK, tid);
        }
    }

    // epilogue: y = acc*(ws*is) + bias; out = dequant(e4m3_round(y/os))*os
    float cscale = ws_p[0] * is_p[0];
    float osv = os_p[0], inv_os = 1.0f / osv;
    int col_base = n0 + warp_n * 64 + (lane & 3) * 2;
    float bv[16];
#pragma unroll
    for (int nt = 0; nt < 8; nt++) {
        bv[nt * 2 + 0] = bias[col_base + nt * 8 + 0];
        bv[nt * 2 + 1] = bias[col_base + nt * 8 + 1];
    }
    int row_base = m0 + warp_m * 32 + (lane >> 2);
#pragma unroll
    for (int mt = 0; mt < 2; mt++) {
#pragma unroll
        for (int h = 0; h < 2; h++) {
            int rr = row_base + mt * 16 + h * 8;
            float* orow = out + (size_t)rr * N_DIM;
#pragma unroll
            for (int nt = 0; nt < 8; nt++) {
                float y0 = acc[mt][nt][h * 2 + 0] * cscale + bv[nt * 2 + 0];
                float y1 = acc[mt][nt][h * 2 + 1] * cscale + bv[nt * 2 + 1];
                unsigned short p;
                uint32_t hq;
                asm("cvt.rn.satfinite.e4m3x2.f32 %0, %1, %2;" : "=h"(p) : "f"(y1 * inv_os), "f"(y0 * inv_os));
                asm("cvt.rn.f16x2.e4m3x2 %0, %1;" : "=r"(hq) : "h"(p));
                float2 f = __half22float2(*reinterpret_cast<__half2*>(&hq));
                float2 o = make_float2(f.x * osv, f.y * osv);
                *reinterpret_cast<float2*>(orow + col_base + nt * 8) = o;
            }
        }
    }
}

extern "C" void kernel_launch(void* const* d_in, const int* in_sizes, int n_in,
                              void* d_out, int out_size) {
    const float* x    = (const float*)d_in[0];
    const float* w    = (const float*)d_in[1];
    const float* ws   = (const float*)d_in[2];
    const float* bias = (const float*)d_in[3];
    const float* is   = (const float*)d_in[4];
    const float* os   = (const float*)d_in[5];
    float* out = (float*)d_out;

    static bool attr_done = false;
    if (!attr_done) {
        cudaFuncSetAttribute(gemm_kernel, cudaFuncAttributeMaxDynamicSharedMemorySize, SMEM_BYTES);
        attr_done = true;
    }

    quant_kernel<<<XBLKS + WBLKS, 256>>>((const float4*)x, (const float4*)w, is);
    gemm_kernel<<<(M_TOTAL / BM) * (N_DIM / BN), 256, SMEM_BYTES>>>(out, bias, ws, is, os);
}

// round 13
// speedup vs baseline: 1.1165x; 1.1165x over previous
#include <cuda.h>
#include <cuda_runtime.h>
#include <cuda_fp16.h>
#include <cstdint>

#define M_TOTAL 16384
#define K_DIM   4096
#define N_DIM   4096
#define BM 128
#define BN 128
#define BK 64
#define STAGES 3
#define KITERS (K_DIM / BK)                 // 64
#define A_STAGE_BYTES (BM * BK * 2)         // 16 KB
#define B_STAGE_BYTES (BN * BK * 2)         // 16 KB
#define STAGE_BYTES (A_STAGE_BYTES + B_STAGE_BYTES)  // 32 KB
#define DATA_OFF 1024
#define SMEM_BYTES (DATA_OFF + STAGES * STAGE_BYTES) // 99328

// fp16 copies of the fp8-rounded operands (scratch: static device arrays)
__device__ __align__(128) __half g_qx[(size_t)M_TOTAL * K_DIM];  // 128 MB
__device__ __align__(128) __half g_qw[(size_t)N_DIM * K_DIM];    // 32 MB

__device__ __forceinline__ uint32_t smem_u32(const void* p) {
    uint32_t a;
    asm("{ .reg .u64 t; cvta.to.shared.u64 t, %1; cvt.u32.u64 %0, t; }" : "=r"(a) : "l"(p));
    return a;
}
__device__ __forceinline__ uint32_t swz(uint32_t off) {
    return off ^ ((off >> 3) & 0x70);  // SW128 for 128-byte rows (matches TMA SWIZZLE_128B)
}

#define LDMATRIX_X4(r0, r1, r2, r3, addr) \
    asm volatile("ldmatrix.sync.aligned.m8n8.x4.shared.b16 {%0,%1,%2,%3}, [%4];" \
        : "=r"(r0), "=r"(r1), "=r"(r2), "=r"(r3) : "r"(addr))
#define MMA16816(c, a, b0, b1) \
    asm volatile("mma.sync.aligned.m16n8k16.row.col.f32.f16.f16.f32 " \
        "{%0,%1,%2,%3}, {%4,%5,%6,%7}, {%8,%9}, {%0,%1,%2,%3};" \
        : "+f"((c)[0]), "+f"((c)[1]), "+f"((c)[2]), "+f"((c)[3]) \
        : "r"((a)[0]), "r"((a)[1]), "r"((a)[2]), "r"((a)[3]), "r"(b0), "r"(b1))

#define MBARRIER_INIT(addr, cnt) \
    asm volatile("mbarrier.init.shared.b64 [%0], %1;" :: "r"((uint32_t)(addr)), "r"((uint32_t)(cnt)) : "memory")
#define MBARRIER_ARRIVE(addr) \
    asm volatile("mbarrier.arrive.shared.b64 _, [%0];" :: "r"((uint32_t)(addr)) : "memory")
#define MBARRIER_EXPECT_TX(addr, bytes) \
    asm volatile("mbarrier.arrive.expect_tx.shared.b64 _, [%0], %1;" :: "r"((uint32_t)(addr)), "r"((uint32_t)(bytes)) : "memory")
#define MBARRIER_WAIT_PARITY(mbar, par) do { \
    uint32_t _m = (uint32_t)(mbar), _p = (uint32_t)(par), _d; \
    asm volatile("{ .reg .pred p; mbarrier.try_wait.parity.acquire.cta.shared::cta.b64 p, [%1], %2; selp.b32 %0, 1, 0, p; }" \
        : "=r"(_d) : "r"(_m), "r"(_p) : "memory"); \
    if (!_d) { \
        asm volatile("{ .reg .pred P1; WL_%=: mbarrier.try_wait.parity.acquire.cta.shared::cta.b64 P1, [%0], %1, 0x989680; @P1 bra.uni WD_%=; bra.uni WL_%=; WD_%=: }" \
            :: "r"(_m), "r"(_p) : "memory"); \
    } \
} while(0)

#define TMA_LOAD_2D(dst, map, c0, c1, mbar) \
    asm volatile("cp.async.bulk.tensor.2d.shared::cta.global.tile.mbarrier::complete_tx::bytes " \
        "[%0], [%1, {%2, %3}], [%4];" \
        :: "r"((uint32_t)(dst)), "l"(map), "r"((int)(c0)), "r"((int)(c1)), "r"((uint32_t)(mbar)) : "memory")

// ---- fused quantize: fp32 -> e4m3 (RN satfinite == clip(+-448)+RN cast) -> fp16 ----
#define XBLKS 2048
#define WBLKS 512
__global__ void quant_kernel(const float4* __restrict__ xsrc, const float4* __restrict__ wsrc,
                             const float* __restrict__ sp) {
    if (blockIdx.x < XBLKS) {
        float inv = 1.0f / sp[0];
        uint2* dst = reinterpret_cast<uint2*>(g_qx);
        int n4 = (M_TOTAL * K_DIM) / 4;
        int stride = XBLKS * blockDim.x;
        for (int i = blockIdx.x * blockDim.x + threadIdx.x; i < n4; i += stride) {
            float4 v = xsrc[i];
            unsigned short lo, hi;
            asm("cvt.rn.satfinite.e4m3x2.f32 %0, %1, %2;" : "=h"(lo) : "f"(v.y * inv), "f"(v.x * inv));
            asm("cvt.rn.satfinite.e4m3x2.f32 %0, %1, %2;" : "=h"(hi) : "f"(v.w * inv), "f"(v.z * inv));
            uint32_t h01, h23;
            asm("cvt.rn.f16x2.e4m3x2 %0, %1;" : "=r"(h01) : "h"(lo));
            asm("cvt.rn.f16x2.e4m3x2 %0, %1;" : "=r"(h23) : "h"(hi));
            dst[i] = make_uint2(h01, h23);
        }
    } else {
        uint2* dst = reinterpret_cast<uint2*>(g_qw);
        int n4 = (N_DIM * K_DIM) / 4;
        int stride = WBLKS * blockDim.x;
        for (int i = (blockIdx.x - XBLKS) * blockDim.x + threadIdx.x; i < n4; i += stride) {
            float4 v = wsrc[i];
            unsigned short lo, hi;
            asm("cvt.rn.satfinite.e4m3x2.f32 %0, %1, %2;" : "=h"(lo) : "f"(v.y), "f"(v.x));
            asm("cvt.rn.satfinite.e4m3x2.f32 %0, %1, %2;" : "=h"(hi) : "f"(v.w), "f"(v.z));
            uint32_t h01, h23;
            asm("cvt.rn.f16x2.e4m3x2 %0, %1;" : "=r"(h01) : "h"(lo));
            asm("cvt.rn.f16x2.e4m3x2 %0, %1;" : "=r"(h23) : "h"(hi));
            dst[i] = make_uint2(h01, h23);
        }
    }
}

// smem layout: full[3] @ sb+0, empty[3] @ sb+24, data @ sb+1024
#define FULL_B(s)  (sb + (s) * 8)
#define EMPTY_B(s) (sb + 24 + (s) * 8)

__global__ void __launch_bounds__(256, 2)
gemm_kernel(const __grid_constant__ CUtensorMap tma_a,
            const __grid_constant__ CUtensorMap tma_b,
            float* __restrict__ out, const float* __restrict__ bias,
            const float* __restrict__ ws_p, const float* __restrict__ is_p,
            const float* __restrict__ os_p)
{
    extern __shared__ unsigned char smem[];
    uint32_t sb = smem_u32(smem);
    int tid = threadIdx.x, lane = tid & 31, wid = tid >> 5;
    int warp_m = wid & 3, warp_n = wid >> 2;   // 4x2 warp grid, warp tile 32x64

    // supertile: groups of 8 m-tiles x 32 n-tiles keep W L2-resident
    int g = blockIdx.x >> 8, r = blockIdx.x & 255;
    int m0 = ((g << 3) + (r & 7)) * BM;
    int n0 = (r >> 3) * BN;

    if (tid == 0) {
        for (int s = 0; s < STAGES; s++) {
            MBARRIER_INIT(FULL_B(s), 1);
            MBARRIER_INIT(EMPTY_B(s), 8);   // one arrive per warp
        }
    }
    __syncthreads();

    if (tid == 0) {   // prologue: fill all 3 stages
        for (int s = 0; s < STAGES; s++) {
            uint32_t abase = sb + DATA_OFF + s * STAGE_BYTES;
            MBARRIER_EXPECT_TX(FULL_B(s), STAGE_BYTES);
            TMA_LOAD_2D(abase, &tma_a, s * BK, m0, FULL_B(s));
            TMA_LOAD_2D(abase + A_STAGE_BYTES, &tma_b, s * BK, n0, FULL_B(s));
        }
    }

    float acc[2][8][4];
#pragma unroll
    for (int i = 0; i < 2; i++)
#pragma unroll
        for (int j = 0; j < 8; j++)
#pragma unroll
            for (int k = 0; k < 4; k++) acc[i][j][k] = 0.0f;

    int s = 0;
    uint32_t ph = 0;   // tracks (it/3)&1
#pragma unroll 1
    for (int it = 0; it < KITERS; it++) {
        MBARRIER_WAIT_PARITY(FULL_B(s), ph);

        uint32_t abase = sb + DATA_OFF + s * STAGE_BYTES;
        uint32_t bbase = abase + A_STAGE_BYTES;
#pragma unroll
        for (int ks = 0; ks < BK / 16; ks++) {
            uint32_t af[2][4], bf[4][4];
            uint32_t cb = (uint32_t)(ks * 32 + ((lane >> 4) << 4));
#pragma unroll
            for (int mt = 0; mt < 2; mt++) {
                uint32_t row = (uint32_t)(warp_m * 32 + mt * 16 + (lane & 15));
                uint32_t addr = abase + swz(row * 128 + cb);
                LDMATRIX_X4(af[mt][0], af[mt][1], af[mt][2], af[mt][3], addr);
            }
#pragma unroll
            for (int p = 0; p < 4; p++) {
                uint32_t row = (uint32_t)(warp_n * 64 + p * 16 + (lane & 15));
                uint32_t addr = bbase + swz(row * 128 + cb);
                // B stored [N][K] (K contiguous) == col-major KxN -> non-trans ldmatrix
                LDMATRIX_X4(bf[p][0], bf[p][1], bf[p][2], bf[p][3], addr);
            }
#pragma unroll
            for (int mt = 0; mt < 2; mt++)
#pragma unroll
                for (int nt = 0; nt < 8; nt++)
                    MMA16816(acc[mt][nt], af[mt], bf[nt >> 1][nt & 1], bf[nt >> 1][2 + (nt & 1)]);
        }

        // this warp is done reading stage s
        if (lane == 0) MBARRIER_ARRIVE(EMPTY_B(s));

        // producer: refill stage s for iteration it+3
        if (tid == 0) {
            int kp = it + STAGES;
            if (kp < KITERS) {
                MBARRIER_WAIT_PARITY(EMPTY_B(s), ph);   // all 8 warps done with s
                MBARRIER_EXPECT_TX(FULL_B(s), STAGE_BYTES);
                TMA_LOAD_2D(abase, &tma_a, kp * BK, m0, FULL_B(s));
                TMA_LOAD_2D(bbase, &tma_b, kp * BK, n0, FULL_B(s));
            }
        }

        if (++s == STAGES) { s = 0; ph ^= 1; }
    }

    // epilogue: y = acc*(ws*is) + bias; out = dequant(e4m3_round(y/os))*os
    float cscale = ws_p[0] * is_p[0];
    float osv = os_p[0], inv_os = 1.0f / osv;
    int col_base = n0 + warp_n * 64 + (lane & 3) * 2;
    float bv[16];
#pragma unroll
    for (int nt = 0; nt < 8; nt++) {
        bv[nt * 2 + 0] = bias[col_base + nt * 8 + 0];
        bv[nt * 2 + 1] = bias[col_base + nt * 8 + 1];
    }
    int row_base = m0 + warp_m * 32 + (lane >> 2);
#pragma unroll
    for (int mt = 0; mt < 2; mt++) {
#pragma unroll
        for (int h = 0; h < 2; h++) {
            int rr = row_base + mt * 16 + h * 8;
            float* orow = out + (size_t)rr * N_DIM;
#pragma unroll
            for (int nt = 0; nt < 8; nt++) {
                float y0 = acc[mt][nt][h * 2 + 0] * cscale + bv[nt * 2 + 0];
                float y1 = acc[mt][nt][h * 2 + 1] * cscale + bv[nt * 2 + 1];
                unsigned short p;
                uint32_t hq;
                asm("cvt.rn.satfinite.e4m3x2.f32 %0, %1, %2;" : "=h"(p) : "f"(y1 * inv_os), "f"(y0 * inv_os));
                asm("cvt.rn.f16x2.e4m3x2 %0, %1;" : "=r"(hq) : "h"(p));
                float2 f = __half22float2(*reinterpret_cast<__half2*>(&hq));
                float2 o = make_float2(f.x * osv, f.y * osv);
                *reinterpret_cast<float2*>(orow + col_base + nt * 8) = o;
            }
        }
    }
}

typedef CUresult (*PFN_encodeTiled)(
    CUtensorMap*, CUtensorMapDataType, cuuint32_t, void*,
    const cuuint64_t*, const cuuint64_t*, const cuuint32_t*, const cuuint32_t*,
    CUtensorMapInterleave, CUtensorMapSwizzle, CUtensorMapL2promotion, CUtensorMapFloatOOBfill);

extern "C" void kernel_launch(void* const* d_in, const int* in_sizes, int n_in,
                              void* d_out, int out_size) {
    const float* x    = (const float*)d_in[0];
    const float* w    = (const float*)d_in[1];
    const float* ws   = (const float*)d_in[2];
    const float* bias = (const float*)d_in[3];
    const float* is   = (const float*)d_in[4];
    const float* os   = (const float*)d_in[5];
    float* out = (float*)d_out;

    static bool init_done = false;
    static CUtensorMap tmA, tmB;
    if (!init_done) {
        cudaFuncSetAttribute(gemm_kernel, cudaFuncAttributeMaxDynamicSharedMemorySize, SMEM_BYTES);

        void* pfn = nullptr;
        cudaDriverEntryPointQueryResult qres;
        cudaGetDriverEntryPointByVersion("cuTensorMapEncodeTiled", &pfn, 12000,
                                         cudaEnableDefault, &qres);
        PFN_encodeTiled encode = (PFN_encodeTiled)pfn;

        void *pA = nullptr, *pB = nullptr;
        cudaGetSymbolAddress(&pA, g_qx);
        cudaGetSymbolAddress(&pB, g_qw);

        // A: [M, K] fp16, K contiguous
        {
            cuuint64_t dims[2]    = {K_DIM, M_TOTAL};
            cuuint64_t strides[1] = {K_DIM * 2};
            cuuint32_t box[2]     = {BK, BM};            // 64 fp16 = 128B inner (SW128 limit)
            cuuint32_t estr[2]    = {1, 1};
            encode(&tmA, CU_TENSOR_MAP_DATA_TYPE_FLOAT16, 2, pA, dims, strides, box, estr,
                   CU_TENSOR_MAP_INTERLEAVE_NONE, CU_TENSOR_MAP_SWIZZLE_128B,
                   CU_TENSOR_MAP_L2_PROMOTION_L2_128B, CU_TENSOR_MAP_FLOAT_OOB_FILL_NONE);
        }
        // B: [N, K] fp16, K contiguous
        {
            cuuint64_t dims[2]    = {K_DIM, N_DIM};
            cuuint64_t strides[1] = {K_DIM * 2};
            cuuint32_t box[2]     = {BK, BN};
            cuuint32_t estr[2]    = {1, 1};
            encode(&tmB, CU_TENSOR_MAP_DATA_TYPE_FLOAT16, 2, pB, dims, strides, box, estr,
                   CU_TENSOR_MAP_INTERLEAVE_NONE, CU_TENSOR_MAP_SWIZZLE_128B,
                   CU_TENSOR_MAP_L2_PROMOTION_L2_128B, CU_TENSOR_MAP_FLOAT_OOB_FILL_NONE);
        }
        init_done = true;
    }

    quant_kernel<<<XBLKS + WBLKS, 256>>>((const float4*)x, (const float4*)w, is);
    gemm_kernel<<<(M_TOTAL / BM) * (N_DIM / BN), 256, SMEM_BYTES>>>(tmA, tmB, out, bias, ws, is, os);
}

// round 14
// speedup vs baseline: 1.2264x; 1.0984x over previous
#include <cuda.h>
#include <cuda_runtime.h>
#include <cuda_fp16.h>
#include <cstdint>

#define M_TOTAL 16384
#define K_DIM   4096
#define N_DIM   4096
#define BM 128
#define BN 128
#define BK 64
#define STAGES 3
#define KITERS (K_DIM / BK)                 // 64
#define A_STAGE_BYTES (BM * BK * 2)         // 16 KB
#define B_STAGE_BYTES (BN * BK * 2)         // 16 KB
#define STAGE_BYTES (A_STAGE_BYTES + B_STAGE_BYTES)  // 32 KB
#define DATA_OFF 1024
#define SMEM_BYTES (DATA_OFF + STAGES * STAGE_BYTES) // 99328

// fp16 copies of the fp8-rounded operands (scratch: static device arrays)
__device__ __align__(128) __half g_qx[(size_t)M_TOTAL * K_DIM];  // 128 MB
__device__ __align__(128) __half g_qw[(size_t)N_DIM * K_DIM];    // 32 MB

__device__ __forceinline__ uint32_t smem_u32(const void* p) {
    uint32_t a;
    asm("{ .reg .u64 t; cvta.to.shared.u64 t, %1; cvt.u32.u64 %0, t; }" : "=r"(a) : "l"(p));
    return a;
}
__device__ __forceinline__ uint32_t swz(uint32_t off) {
    return off ^ ((off >> 3) & 0x70);  // SW128 (matches TMA SWIZZLE_128B)
}

#define LDMATRIX_X4(r0, r1, r2, r3, addr) \
    asm volatile("ldmatrix.sync.aligned.m8n8.x4.shared.b16 {%0,%1,%2,%3}, [%4];" \
        : "=r"(r0), "=r"(r1), "=r"(r2), "=r"(r3) : "r"(addr))
#define MMA16816(c, a, b0, b1) \
    asm volatile("mma.sync.aligned.m16n8k16.row.col.f32.f16.f16.f32 " \
        "{%0,%1,%2,%3}, {%4,%5,%6,%7}, {%8,%9}, {%0,%1,%2,%3};" \
        : "+f"((c)[0]), "+f"((c)[1]), "+f"((c)[2]), "+f"((c)[3]) \
        : "r"((a)[0]), "r"((a)[1]), "r"((a)[2]), "r"((a)[3]), "r"(b0), "r"(b1))

#define MBARRIER_INIT(addr, cnt) \
    asm volatile("mbarrier.init.shared.b64 [%0], %1;" :: "r"((uint32_t)(addr)), "r"((uint32_t)(cnt)) : "memory")
#define MBARRIER_ARRIVE(addr) \
    asm volatile("mbarrier.arrive.shared.b64 _, [%0];" :: "r"((uint32_t)(addr)) : "memory")
#define MBARRIER_EXPECT_TX(addr, bytes) \
    asm volatile("mbarrier.arrive.expect_tx.shared.b64 _, [%0], %1;" :: "r"((uint32_t)(addr)), "r"((uint32_t)(bytes)) : "memory")
#define MBARRIER_WAIT_PARITY(mbar, par) do { \
    uint32_t _m = (uint32_t)(mbar), _p = (uint32_t)(par), _d; \
    asm volatile("{ .reg .pred p; mbarrier.try_wait.parity.acquire.cta.shared::cta.b64 p, [%1], %2; selp.b32 %0, 1, 0, p; }" \
        : "=r"(_d) : "r"(_m), "r"(_p) : "memory"); \
    if (!_d) { \
        asm volatile("{ .reg .pred P1; WL_%=: mbarrier.try_wait.parity.acquire.cta.shared::cta.b64 P1, [%0], %1, 0x989680; @P1 bra.uni WD_%=; bra.uni WL_%=; WD_%=: }" \
            :: "r"(_m), "r"(_p) : "memory"); \
    } \
} while(0)

#define TMA_LOAD_2D(dst, map, c0, c1, mbar) \
    asm volatile("cp.async.bulk.tensor.2d.shared::cta.global.tile.mbarrier::complete_tx::bytes " \
        "[%0], [%1, {%2, %3}], [%4];" \
        :: "r"((uint32_t)(dst)), "l"(map), "r"((int)(c0)), "r"((int)(c1)), "r"((uint32_t)(mbar)) : "memory")

// ---- fused quantize: fp32 -> e4m3 (RN satfinite == clip(+-448)+RN cast) -> fp16 ----
#define XBLKS 2048
#define WBLKS 512
__global__ void quant_kernel(const float4* __restrict__ xsrc, const float4* __restrict__ wsrc,
                             const float* __restrict__ sp) {
    if (blockIdx.x < XBLKS) {
        float inv = 1.0f / sp[0];
        uint2* dst = reinterpret_cast<uint2*>(g_qx);
        int n4 = (M_TOTAL * K_DIM) / 4;
        int stride = XBLKS * blockDim.x;
        for (int i = blockIdx.x * blockDim.x + threadIdx.x; i < n4; i += stride) {
            float4 v = xsrc[i];
            unsigned short lo, hi;
            asm("cvt.rn.satfinite.e4m3x2.f32 %0, %1, %2;" : "=h"(lo) : "f"(v.y * inv), "f"(v.x * inv));
            asm("cvt.rn.satfinite.e4m3x2.f32 %0, %1, %2;" : "=h"(hi) : "f"(v.w * inv), "f"(v.z * inv));
            uint32_t h01, h23;
            asm("cvt.rn.f16x2.e4m3x2 %0, %1;" : "=r"(h01) : "h"(lo));
            asm("cvt.rn.f16x2.e4m3x2 %0, %1;" : "=r"(h23) : "h"(hi));
            dst[i] = make_uint2(h01, h23);
        }
    } else {
        uint2* dst = reinterpret_cast<uint2*>(g_qw);
        int n4 = (N_DIM * K_DIM) / 4;
        int stride = WBLKS * blockDim.x;
        for (int i = (blockIdx.x - XBLKS) * blockDim.x + threadIdx.x; i < n4; i += stride) {
            float4 v = wsrc[i];
            unsigned short lo, hi;
            asm("cvt.rn.satfinite.e4m3x2.f32 %0, %1, %2;" : "=h"(lo) : "f"(v.y), "f"(v.x));
            asm("cvt.rn.satfinite.e4m3x2.f32 %0, %1, %2;" : "=h"(hi) : "f"(v.w), "f"(v.z));
            uint32_t h01, h23;
            asm("cvt.rn.f16x2.e4m3x2 %0, %1;" : "=r"(h01) : "h"(lo));
            asm("cvt.rn.f16x2.e4m3x2 %0, %1;" : "=r"(h23) : "h"(hi));
            dst[i] = make_uint2(h01, h23);
        }
    }
}

// smem layout: full[3] @ sb+0, empty[3] @ sb+24, data @ sb+1024
#define FULL_B(s)  (sb + (s) * 8)
#define EMPTY_B(s) (sb + 24 + (s) * 8)

__global__ void __launch_bounds__(256, 2)
gemm_kernel(const __grid_constant__ CUtensorMap tma_a,
            const __grid_constant__ CUtensorMap tma_b,
            float* __restrict__ out, const float* __restrict__ bias,
            const float* __restrict__ ws_p, const float* __restrict__ is_p,
            const float* __restrict__ os_p)
{
    extern __shared__ unsigned char smem[];
    uint32_t sb = smem_u32(smem);
    int tid = threadIdx.x, lane = tid & 31, wid = tid >> 5;
    int warp_m = wid & 3, warp_n = wid >> 2;   // 4x2 warp grid, warp tile 32x64

    // supertile: groups of 8 m-tiles x 32 n-tiles keep W L2-resident
    int g = blockIdx.x >> 8, r = blockIdx.x & 255;
    int m0 = ((g << 3) + (r & 7)) * BM;
    int n0 = (r >> 3) * BN;

    if (tid == 0) {
        for (int s = 0; s < STAGES; s++) {
            MBARRIER_INIT(FULL_B(s), 1);
            MBARRIER_INIT(EMPTY_B(s), 8);   // one arrive per warp
        }
    }
    __syncthreads();

    if (tid == 0) {   // prologue: fill all 3 stages
        for (int s = 0; s < STAGES; s++) {
            uint32_t abase = sb + DATA_OFF + s * STAGE_BYTES;
            MBARRIER_EXPECT_TX(FULL_B(s), STAGE_BYTES);
            TMA_LOAD_2D(abase, &tma_a, s * BK, m0, FULL_B(s));
            TMA_LOAD_2D(abase + A_STAGE_BYTES, &tma_b, s * BK, n0, FULL_B(s));
        }
    }

    float acc[2][8][4];
#pragma unroll
    for (int i = 0; i < 2; i++)
#pragma unroll
        for (int j = 0; j < 8; j++)
#pragma unroll
            for (int k = 0; k < 4; k++) acc[i][j][k] = 0.0f;

// one pipeline iteration with compile-time stage S and parity PH
#define ITER(S, PH, IT) do { \
    MBARRIER_WAIT_PARITY(FULL_B(S), (PH)); \
    uint32_t abase = sb + DATA_OFF + (S) * STAGE_BYTES; \
    uint32_t bbase = abase + A_STAGE_BYTES; \
    _Pragma("unroll") \
    for (int ks = 0; ks < BK / 16; ks++) { \
        uint32_t af[2][4], bf[4][4]; \
        uint32_t cb = (uint32_t)(ks * 32 + ((lane >> 4) << 4)); \
        _Pragma("unroll") \
        for (int mt = 0; mt < 2; mt++) { \
            uint32_t row = (uint32_t)(warp_m * 32 + mt * 16 + (lane & 15)); \
            uint32_t addr = abase + swz(row * 128 + cb); \
            LDMATRIX_X4(af[mt][0], af[mt][1], af[mt][2], af[mt][3], addr); \
        } \
        _Pragma("unroll") \
        for (int p = 0; p < 4; p++) { \
            uint32_t row = (uint32_t)(warp_n * 64 + p * 16 + (lane & 15)); \
            uint32_t addr = bbase + swz(row * 128 + cb); \
            LDMATRIX_X4(bf[p][0], bf[p][1], bf[p][2], bf[p][3], addr); \
        } \
        _Pragma("unroll") \
        for (int mt = 0; mt < 2; mt++) \
            _Pragma("unroll") \
            for (int nt = 0; nt < 8; nt++) \
                MMA16816(acc[mt][nt], af[mt], bf[nt >> 1][nt & 1], bf[nt >> 1][2 + (nt & 1)]); \
    } \
    if (lane == 0) MBARRIER_ARRIVE(EMPTY_B(S)); \
    if (tid == 0) { \
        int kp = (IT) + STAGES; \
        if (kp < KITERS) { \
            MBARRIER_WAIT_PARITY(EMPTY_B(S), (PH)); \
            MBARRIER_EXPECT_TX(FULL_B(S), STAGE_BYTES); \
            TMA_LOAD_2D(abase, &tma_a, kp * BK, m0, FULL_B(S)); \
            TMA_LOAD_2D(bbase, &tma_b, kp * BK, n0, FULL_B(S)); \
        } \
    } \
} while (0)

    {
        uint32_t ph = 0;
#pragma unroll 1
        for (int base = 0; base < 63; base += 3) {   // 21 groups of 3
            ITER(0, ph, base);
            ITER(1, ph, base + 1);
            ITER(2, ph, base + 2);
            ph ^= 1;
        }
        ITER(0, 1u, 63);   // tail: iter 63 = stage 0, parity (63/3)&1 = 1
    }

    // epilogue: y = acc*(ws*is) + bias; out = dequant(e4m3_round(y/os))*os
    float cscale = ws_p[0] * is_p[0];
    float osv = os_p[0], inv_os = 1.0f / osv;
    int col_base = n0 + warp_n * 64 + (lane & 3) * 2;
    float bv[16];
#pragma unroll
    for (int nt = 0; nt < 8; nt++) {
        bv[nt * 2 + 0] = bias[col_base + nt * 8 + 0];
        bv[nt * 2 + 1] = bias[col_base + nt * 8 + 1];
    }
    int row_base = m0 + warp_m * 32 + (lane >> 2);
#pragma unroll
    for (int mt = 0; mt < 2; mt++) {
#pragma unroll
        for (int h = 0; h < 2; h++) {
            int rr = row_base + mt * 16 + h * 8;
            float* orow = out + (size_t)rr * N_DIM;
#pragma unroll
            for (int nt = 0; nt < 8; nt++) {
                float y0 = acc[mt][nt][h * 2 + 0] * cscale + bv[nt * 2 + 0];
                float y1 = acc[mt][nt][h * 2 + 1] * cscale + bv[nt * 2 + 1];
                unsigned short p;
                uint32_t hq;
                asm("cvt.rn.satfinite.e4m3x2.f32 %0, %1, %2;" : "=h"(p) : "f"(y1 * inv_os), "f"(y0 * inv_os));
                asm("cvt.rn.f16x2.e4m3x2 %0, %1;" : "=r"(hq) : "h"(p));
                float2 f = __half22float2(*reinterpret_cast<__half2*>(&hq));
                float2 o = make_float2(f.x * osv, f.y * osv);
                *reinterpret_cast<float2*>(orow + col_base + nt * 8) = o;
            }
        }
    }
}

typedef CUresult (*PFN_encodeTiled)(
    CUtensorMap*, CUtensorMapDataType, cuuint32_t, void*,
    const cuuint64_t*, const cuuint64_t*, const cuuint32_t*, const cuuint32_t*,
    CUtensorMapInterleave, CUtensorMapSwizzle, CUtensorMapL2promotion, CUtensorMapFloatOOBfill);

extern "C" void kernel_launch(void* const* d_in, const int* in_sizes, int n_in,
                              void* d_out, int out_size) {
    const float* x    = (const float*)d_in[0];
    const float* w    = (const float*)d_in[1];
    const float* ws   = (const float*)d_in[2];
    const float* bias = (const float*)d_in[3];
    const float* is   = (const float*)d_in[4];
    const float* os   = (const float*)d_in[5];
    float* out = (float*)d_out;

    static bool init_done = false;
    static CUtensorMap tmA, tmB;
    if (!init_done) {
        cudaFuncSetAttribute(gemm_kernel, cudaFuncAttributeMaxDynamicSharedMemorySize, SMEM_BYTES);

        void* pfn = nullptr;
        cudaDriverEntryPointQueryResult qres;
        cudaGetDriverEntryPointByVersion("cuTensorMapEncodeTiled", &pfn, 12000,
                                         cudaEnableDefault, &qres);
        PFN_encodeTiled encode = (PFN_encodeTiled)pfn;

        void *pA = nullptr, *pB = nullptr;
        cudaGetSymbolAddress(&pA, g_qx);
        cudaGetSymbolAddress(&pB, g_qw);

        {
            cuuint64_t dims[2]    = {K_DIM, M_TOTAL};
            cuuint64_t strides[1] = {K_DIM * 2};
            cuuint32_t box[2]     = {BK, BM};
            cuuint32_t estr[2]    = {1, 1};
            encode(&tmA, CU_TENSOR_MAP_DATA_TYPE_FLOAT16, 2, pA, dims, strides, box, estr,
                   CU_TENSOR_MAP_INTERLEAVE_NONE, CU_TENSOR_MAP_SWIZZLE_128B,
                   CU_TENSOR_MAP_L2_PROMOTION_L2_128B, CU_TENSOR_MAP_FLOAT_OOB_FILL_NONE);
        }
        {
            cuuint64_t dims[2]    = {K_DIM, N_DIM};
            cuuint64_t strides[1] = {K_DIM * 2};
            cuuint32_t box[2]     = {BK, BN};
            cuuint32_t estr[2]    = {1, 1};
            encode(&tmB, CU_TENSOR_MAP_DATA_TYPE_FLOAT16, 2, pB, dims, strides, box, estr,
                   CU_TENSOR_MAP_INTERLEAVE_NONE, CU_TENSOR_MAP_SWIZZLE_128B,
                   CU_TENSOR_MAP_L2_PROMOTION_L2_128B, CU_TENSOR_MAP_FLOAT_OOB_FILL_NONE);
        }
        init_done = true;
    }

    quant_kernel<<<XBLKS + WBLKS, 256>>>((const float4*)x, (const float4*)w, is);
    gemm_kernel<<<(M_TOTAL / BM) * (N_DIM / BN), 256, SMEM_BYTES>>>(tmA, tmB, out, bias, ws, is, os);
}